// round 4
// baseline (speedup 1.0000x reference)
#include <cuda_runtime.h>

#define THREADS  256
#define WPB      (THREADS / 32)     // 8 warps per block, 1 row per warp
#define NTERMS   48
#define NBUCKETS 64
#define DIM4     128                // 512 floats = 128 float4

// All zero at module load; the finalizing block restores them to zero every
// launch, so graph replays are deterministic with no init kernel.
__device__ double   g_sum[NBUCKETS];
__device__ double   g_cnt[NBUCKETS];
__device__ unsigned g_ticket;
__device__ int      g_flag32;   // 1 => target buffer is int32 (jax demoted)

// C = 255*ln2 + lgamma(256) - 256*ln(2*pi)
#define LOSS_C 867.968103160394f

__device__ __forceinline__ float dot4(float4 a, float4 b) {
    return a.x*b.x + a.y*b.y + a.z*b.z + a.w*b.w;
}

// Detect whether target buffer is int64 or int32. Reads first n/2 int64 words
// = first n*4 bytes, in-bounds for both layouts.
__global__ void nll_detect(const long long* __restrict__ t64, int n_half, long long vocab) {
    int i = blockIdx.x * blockDim.x + threadIdx.x;
    if (i < n_half) {
        long long v = t64[i];
        if (v < 0 || v >= vocab) g_flag32 = 1;   // all writers store 1: race-free
    }
}

__global__ void __launch_bounds__(THREADS)
nll_main(const float* __restrict__ preds,
         const void*  __restrict__ target,
         const float* __restrict__ emb,
         float* __restrict__ out, int out_size, int n)
{
    int tid  = threadIdx.x;
    int lane = tid & 31;
    int w    = tid >> 5;
    int row  = blockIdx.x * WPB + w;

    float loss = 0.0f;
    int   ok   = 0;

    if (row < n) {
        // Target load first (starts the gather-address chain ASAP).
        long long t_l = 0;
        if (lane == 0) {
            t_l = g_flag32 ? (long long)((const int*)target)[row]
                           : ((const long long*)target)[row];
        }

        // Preds loads do not depend on the target — issue immediately.
        const float4* p = reinterpret_cast<const float4*>(preds) + (size_t)row * DIM4 + lane;
        float4 a0 = p[0], a1 = p[32], a2 = p[64], a3 = p[96];

        long long t = __shfl_sync(0xffffffffu, t_l, 0);
        const float4* e = reinterpret_cast<const float4*>(emb) + (size_t)t * DIM4 + lane;
        float4 b0 = e[0], b1 = e[32], b2 = e[64], b3 = e[96];

        float ss = dot4(a0,a0) + dot4(a1,a1) + dot4(a2,a2) + dot4(a3,a3);
        float dt = dot4(a0,b0) + dot4(a1,b1) + dot4(a2,b2) + dot4(a3,b3);

        #pragma unroll
        for (int o = 16; o > 0; o >>= 1) {
            ss += __shfl_down_sync(0xffffffffu, ss, o);
            dt += __shfl_down_sync(0xffffffffu, dt, o);
        }

        if (lane == 0 && t != 1) {   // PAD_ID == 1
            float z = sqrtf(ss);
            float x = 0.25f * ss;
            // S = sum_j x^j / (j! * (256)_j); constants fold at compile time.
            float S = 1.0f, term = 1.0f;
            #pragma unroll
            for (int j = 1; j < NTERMS; j++) {
                term *= x * (1.0f / ((float)j * (255.0f + (float)j)));
                S += term;
            }
            loss = logf(S) - z - dt - LOSS_C;
            ok = 1;
        }
    }

    if (ok) {
        int b = (blockIdx.x * WPB + w) & (NBUCKETS - 1);
        atomicAdd(&g_sum[b], (double)loss);
        atomicAdd(&g_cnt[b], 1.0);
        __threadfence();   // release this warp's contributions
    }

    // ---- last-block finalize + state reset ----
    __syncthreads();
    __shared__ unsigned s_tkt;
    if (tid == 0) s_tkt = atomicAdd(&g_ticket, 1u);
    __syncthreads();

    if (s_tkt == gridDim.x - 1) {
        __threadfence();   // acquire: see all blocks' atomics
        double s = 0.0, c = 0.0;
        if (tid < NBUCKETS) { s = g_sum[tid]; c = g_cnt[tid]; }
        #pragma unroll
        for (int o = 16; o > 0; o >>= 1) {
            s += __shfl_down_sync(0xffffffffu, s, o);
            c += __shfl_down_sync(0xffffffffu, c, o);
        }
        __shared__ double sh_s[2], sh_c[2];
        if (tid < NBUCKETS && lane == 0) { sh_s[tid >> 5] = s; sh_c[tid >> 5] = c; }
        __syncthreads();
        if (tid == 0) {
            float r = (float)((sh_s[0] + sh_s[1]) / (sh_c[0] + sh_c[1]));
            for (int i = 0; i < out_size; i++) out[i] = r;
            g_ticket = 0u;
            g_flag32 = 0;
        }
        if (tid < NBUCKETS) { g_sum[tid] = 0.0; g_cnt[tid] = 0.0; }
    }
}

extern "C" void kernel_launch(void* const* d_in, const int* in_sizes, int n_in,
                              void* d_out, int out_size) {
    const float* preds  = (const float*)d_in[0];
    const void*  target = d_in[1];
    const float* emb    = (const float*)d_in[2];
    int n = in_sizes[1];                              // B*S rows
    long long vocab = (long long)(in_sizes[2] / 512); // rows of emb table

    int nd = n / 2;
    nll_detect<<<(nd + 255) / 256, 256>>>((const long long*)target, nd, vocab);
    int blocks = (n + WPB - 1) / WPB;
    nll_main<<<blocks, THREADS>>>(preds, target, emb, (float*)d_out, out_size, n);
}

// round 5
// speedup vs baseline: 1.1355x; 1.1355x over previous
#include <cuda_runtime.h>

#define THREADS  256
#define WPB      8          // warps per block
#define RPW      2          // rows per warp (parallel halves)
#define RPB      (WPB * RPW)
#define NTERMS   16
#define NBUCKETS 64
#define DIM4     128        // 512 floats = 128 float4

// Zero at module load; finalizing warp restores zeros each launch
// (graph-replay deterministic, no init kernel).
__device__ double   g_sum[NBUCKETS];
__device__ double   g_cnt[NBUCKETS];
__device__ unsigned g_ticket;
__device__ int      g_flag32;   // 1 => target buffer is int32 (jax demoted)

// C = 255*ln2 + lgamma(256) - 256*ln(2*pi)
#define LOSS_C 867.968103160394f

__device__ __forceinline__ float dot4(float4 a, float4 b) {
    return a.x*b.x + a.y*b.y + a.z*b.z + a.w*b.w;
}

// Detect whether target buffer is int64 or int32. Reads first n/2 int64 words
// = first n*4 bytes, in-bounds for both layouts.
__global__ void nll_detect(const long long* __restrict__ t64, int n_half, long long vocab) {
    int i = blockIdx.x * blockDim.x + threadIdx.x;
    if (i < n_half) {
        long long v = t64[i];
        if (v < 0 || v >= vocab) g_flag32 = 1;   // all writers store 1: race-free
    }
}

__global__ void __launch_bounds__(THREADS)
nll_main(const float* __restrict__ preds,
         const void*  __restrict__ target,
         const float* __restrict__ emb,
         float* __restrict__ out, int out_size, int n, unsigned total_warps)
{
    int tid   = threadIdx.x;
    int lane  = tid & 31;
    int half  = lane >> 4;          // 0: row0, 1: row1
    int sub   = lane & 15;          // lane within half
    int w     = tid >> 5;
    unsigned wg = blockIdx.x * WPB + w;     // global warp id
    int row   = (int)wg * RPW + half;
    int rowc  = row < n ? row : 0;          // clamp; invalid rows forced to PAD below
    int flag  = g_flag32;                   // uniform per warp

    // Lanes 0,1 load the warp's two targets; broadcast to halves.
    long long t_l = 1;
    if (lane < RPW) {
        int r = (int)wg * RPW + lane;
        if (r < n) {
            t_l = flag ? (long long)((const int*)target)[r]
                       : ((const long long*)target)[r];
        }
    }

    // Front-batched preds loads (independent of target).
    const float4* p = reinterpret_cast<const float4*>(preds) + (size_t)rowc * DIM4 + sub;
    float4 a0 = p[0],  a1 = p[16], a2 = p[32], a3 = p[48];
    float4 a4 = p[64], a5 = p[80], a6 = p[96], a7 = p[112];

    long long t = __shfl_sync(0xffffffffu, t_l, half);
    if (row >= n) t = 1;                    // PAD => contributes nothing

    const float4* e = reinterpret_cast<const float4*>(emb) + (size_t)t * DIM4 + sub;
    float4 b0 = e[0],  b1 = e[16], b2 = e[32], b3 = e[48];
    float4 b4 = e[64], b5 = e[80], b6 = e[96], b7 = e[112];

    float ss = dot4(a0,a0)+dot4(a1,a1)+dot4(a2,a2)+dot4(a3,a3)
             + dot4(a4,a4)+dot4(a5,a5)+dot4(a6,a6)+dot4(a7,a7);
    float dt = dot4(a0,b0)+dot4(a1,b1)+dot4(a2,b2)+dot4(a3,b3)
             + dot4(a4,b4)+dot4(a5,b5)+dot4(a6,b6)+dot4(a7,b7);

    // Reduce within each 16-lane half.
    #pragma unroll
    for (int o = 8; o > 0; o >>= 1) {
        ss += __shfl_down_sync(0xffffffffu, ss, o, 16);
        dt += __shfl_down_sync(0xffffffffu, dt, o, 16);
    }

    // Lanes 0 and 16 compute their row's loss SIMD-simultaneously.
    float loss = 0.0f, cnt = 0.0f;
    if (sub == 0 && t != 1) {   // PAD_ID == 1
        float z = sqrtf(ss);
        float x = 0.25f * ss;
        // S = sum_j x^j / (j! * (256)_j); x ~ 128 => converged well before j=16.
        float S = 1.0f, term = 1.0f;
        #pragma unroll
        for (int j = 1; j < NTERMS; j++) {
            term *= x * (1.0f / ((float)j * (255.0f + (float)j)));
            S += term;
        }
        loss = logf(S) - z - dt - LOSS_C;
        cnt  = 1.0f;
    }
    // Fold row1 (lane 16) into lane 0.
    loss += __shfl_down_sync(0xffffffffu, loss, 16);
    cnt  += __shfl_down_sync(0xffffffffu, cnt,  16);

    if (lane == 0) {
        if (cnt > 0.0f) {
            int b = wg & (NBUCKETS - 1);
            atomicAdd(&g_sum[b], (double)loss);
            atomicAdd(&g_cnt[b], (double)cnt);
        }
        __threadfence();                     // release before ticket
    }

    // ---- last-WARP finalize + state reset (no __syncthreads anywhere) ----
    unsigned tkt = 0;
    if (lane == 0) tkt = atomicAdd(&g_ticket, 1u);
    tkt = __shfl_sync(0xffffffffu, tkt, 0);

    if (tkt == total_warps - 1) {
        __threadfence();                     // acquire all blocks' atomics
        double s = g_sum[lane] + g_sum[lane + 32];
        double c = g_cnt[lane] + g_cnt[lane + 32];
        #pragma unroll
        for (int o = 16; o > 0; o >>= 1) {
            s += __shfl_down_sync(0xffffffffu, s, o);
            c += __shfl_down_sync(0xffffffffu, c, o);
        }
        if (lane == 0) {
            float r = (float)(s / c);
            for (int i = 0; i < out_size; i++) out[i] = r;
            g_ticket = 0u;
            g_flag32 = 0;
        }
        g_sum[lane] = 0.0; g_sum[lane + 32] = 0.0;
        g_cnt[lane] = 0.0; g_cnt[lane + 32] = 0.0;
    }
}

extern "C" void kernel_launch(void* const* d_in, const int* in_sizes, int n_in,
                              void* d_out, int out_size) {
    const float* preds  = (const float*)d_in[0];
    const void*  target = d_in[1];
    const float* emb    = (const float*)d_in[2];
    int n = in_sizes[1];                              // B*S rows
    long long vocab = (long long)(in_sizes[2] / 512); // rows of emb table

    int nd = n / 2;
    nll_detect<<<(nd + 255) / 256, 256>>>((const long long*)target, nd, vocab);
    int blocks = (n + RPB - 1) / RPB;
    unsigned total_warps = (unsigned)blocks * WPB;
    nll_main<<<blocks, THREADS>>>(preds, target, emb, (float*)d_out,
                                  out_size, n, total_warps);
}